// round 1
// baseline (speedup 1.0000x reference)
#include <cuda_runtime.h>
#include <cstdint>

#define D_MODEL 1024
#define NHEAD   16
#define DK      64
#define BATCH   2
#define SEQ     2048
#define MTOT    (BATCH * SEQ)   // 4096

// Scratch (device globals — no runtime allocation allowed)
__device__ float g_q[MTOT * D_MODEL];
__device__ float g_k[MTOT * D_MODEL];
__device__ float g_v[MTOT * D_MODEL];
__device__ float g_att[MTOT * D_MODEL];

// ============================================================================
// SGEMM: out[M,N] = X[M,K] * W[N,K]^T + bias[N]
// 128x128 block tile, K-tile 8, double-buffered smem, 256 threads, 8x8/thread
// ============================================================================
__global__ __launch_bounds__(256) void sgemm_bias(
    const float* __restrict__ X, const float* __restrict__ W,
    const float* __restrict__ bias, float* __restrict__ out,
    int M, int N, int K)
{
    __shared__ float As[2][8][132];
    __shared__ float Bs[2][8][132];

    const int tid  = threadIdx.x;
    const int m0   = blockIdx.y * 128;
    const int n0   = blockIdx.x * 128;
    const int lrow = tid >> 1;          // 0..127
    const int lcol = (tid & 1) << 2;    // 0 or 4
    const int tx   = tid & 15;
    const int ty   = tid >> 4;

    float acc[8][8];
    #pragma unroll
    for (int i = 0; i < 8; i++)
        #pragma unroll
        for (int j = 0; j < 8; j++) acc[i][j] = 0.0f;

    // prologue: load tile 0
    {
        float4 a = *(const float4*)&X[(size_t)(m0 + lrow) * K + lcol];
        float4 b = *(const float4*)&W[(size_t)(n0 + lrow) * K + lcol];
        As[0][lcol + 0][lrow] = a.x; As[0][lcol + 1][lrow] = a.y;
        As[0][lcol + 2][lrow] = a.z; As[0][lcol + 3][lrow] = a.w;
        Bs[0][lcol + 0][lrow] = b.x; Bs[0][lcol + 1][lrow] = b.y;
        Bs[0][lcol + 2][lrow] = b.z; Bs[0][lcol + 3][lrow] = b.w;
    }
    __syncthreads();

    int buf = 0;
    for (int kt = 0; kt < K; kt += 8) {
        if (kt + 8 < K) {
            float4 a = *(const float4*)&X[(size_t)(m0 + lrow) * K + kt + 8 + lcol];
            float4 b = *(const float4*)&W[(size_t)(n0 + lrow) * K + kt + 8 + lcol];
            int nb = buf ^ 1;
            As[nb][lcol + 0][lrow] = a.x; As[nb][lcol + 1][lrow] = a.y;
            As[nb][lcol + 2][lrow] = a.z; As[nb][lcol + 3][lrow] = a.w;
            Bs[nb][lcol + 0][lrow] = b.x; Bs[nb][lcol + 1][lrow] = b.y;
            Bs[nb][lcol + 2][lrow] = b.z; Bs[nb][lcol + 3][lrow] = b.w;
        }
        #pragma unroll
        for (int k = 0; k < 8; k++) {
            float a[8], b[8];
            *(float4*)&a[0] = *(const float4*)&As[buf][k][ty * 8];
            *(float4*)&a[4] = *(const float4*)&As[buf][k][ty * 8 + 4];
            *(float4*)&b[0] = *(const float4*)&Bs[buf][k][tx * 8];
            *(float4*)&b[4] = *(const float4*)&Bs[buf][k][tx * 8 + 4];
            #pragma unroll
            for (int i = 0; i < 8; i++)
                #pragma unroll
                for (int j = 0; j < 8; j++)
                    acc[i][j] += a[i] * b[j];
        }
        __syncthreads();
        buf ^= 1;
    }

    // epilogue with bias
    float bv[8];
    #pragma unroll
    for (int j = 0; j < 8; j++) bv[j] = bias[n0 + tx * 8 + j];

    #pragma unroll
    for (int i = 0; i < 8; i++) {
        int row = m0 + ty * 8 + i;
        #pragma unroll
        for (int j = 0; j < 8; j += 4) {
            float4 r;
            r.x = acc[i][j + 0] + bv[j + 0];
            r.y = acc[i][j + 1] + bv[j + 1];
            r.z = acc[i][j + 2] + bv[j + 2];
            r.w = acc[i][j + 3] + bv[j + 3];
            *(float4*)&out[(size_t)row * N + n0 + tx * 8 + j] = r;
        }
    }
}

// ============================================================================
// Flash-attention (fp32): one CTA per (b, h, 64-query tile).
// Q/K staged transposed [d][q] in smem; V row-major; online softmax.
// smem layout (floats): Qs[64*68] Ks[64*68] Vs[64*68] Ss[64*68] m[64] l[64] f[64]
// ============================================================================
#define TPAD 68

__global__ __launch_bounds__(256) void attn_kernel(
    const float* __restrict__ Qp, const float* __restrict__ Kp,
    const float* __restrict__ Vp, float* __restrict__ Op)
{
    extern __shared__ float sm[];
    float* Qs  = sm;
    float* Ks  = sm + 64 * TPAD;
    float* Vs  = sm + 2 * 64 * TPAD;
    float* Ss  = sm + 3 * 64 * TPAD;
    float* m_s = sm + 4 * 64 * TPAD;
    float* l_s = m_s + 64;
    float* f_s = l_s + 64;

    const int tid = threadIdx.x;
    const int tx  = tid & 15;
    const int ty  = tid >> 4;
    const int bh  = blockIdx.y;
    const int b   = bh >> 4;
    const int h   = bh & 15;
    const int q0  = blockIdx.x * 64;
    const float scale = 0.125f;  // 1/sqrt(dk)=1/8

    const float* Qbase = Qp + (size_t)(b * SEQ + q0) * D_MODEL + h * DK;

    // Load Q tile transposed, pre-scaled
    #pragma unroll
    for (int i = 0; i < 4; i++) {
        int idx = i * 1024 + tid * 4;
        int q = idx >> 6, d = idx & 63;
        float4 v = *(const float4*)(Qbase + (size_t)q * D_MODEL + d);
        Qs[(d + 0) * TPAD + q] = v.x * scale;
        Qs[(d + 1) * TPAD + q] = v.y * scale;
        Qs[(d + 2) * TPAD + q] = v.z * scale;
        Qs[(d + 3) * TPAD + q] = v.w * scale;
    }
    if (tid < 64) {
        m_s[tid] = __int_as_float(0xff800000);  // -inf
        l_s[tid] = 0.0f;
    }

    float o[4][4] = {};
    const int qm = ty * 4;
    const int cn = tx * 4;   // key column in S phase, d column in PV phase

    for (int kt = 0; kt < SEQ; kt += 64) {
        __syncthreads();  // protect Ks/Vs/Ss reuse across iterations (and Q load on iter 0)

        const float* Kbase = Kp + (size_t)(b * SEQ + kt) * D_MODEL + h * DK;
        const float* Vbase = Vp + (size_t)(b * SEQ + kt) * D_MODEL + h * DK;
        #pragma unroll
        for (int i = 0; i < 4; i++) {
            int idx = i * 1024 + tid * 4;
            int r = idx >> 6, d = idx & 63;
            float4 kv = *(const float4*)(Kbase + (size_t)r * D_MODEL + d);
            Ks[(d + 0) * TPAD + r] = kv.x;
            Ks[(d + 1) * TPAD + r] = kv.y;
            Ks[(d + 2) * TPAD + r] = kv.z;
            Ks[(d + 3) * TPAD + r] = kv.w;
            float4 vv = *(const float4*)(Vbase + (size_t)r * D_MODEL + d);
            *(float4*)&Vs[r * TPAD + d] = vv;
        }
        __syncthreads();

        // S tile = (Q*scale) @ K^T   -> s[4][4]
        float s[4][4] = {};
        #pragma unroll
        for (int d = 0; d < 64; d++) {
            float4 a = *(const float4*)&Qs[d * TPAD + qm];
            float4 bb = *(const float4*)&Ks[d * TPAD + cn];
            s[0][0] += a.x * bb.x; s[0][1] += a.x * bb.y; s[0][2] += a.x * bb.z; s[0][3] += a.x * bb.w;
            s[1][0] += a.y * bb.x; s[1][1] += a.y * bb.y; s[1][2] += a.y * bb.z; s[1][3] += a.y * bb.w;
            s[2][0] += a.z * bb.x; s[2][1] += a.z * bb.y; s[2][2] += a.z * bb.z; s[2][3] += a.z * bb.w;
            s[3][0] += a.w * bb.x; s[3][1] += a.w * bb.y; s[3][2] += a.w * bb.z; s[3][3] += a.w * bb.w;
        }
        #pragma unroll
        for (int i = 0; i < 4; i++)
            *(float4*)&Ss[(qm + i) * TPAD + cn] = *(float4*)&s[i][0];
        __syncthreads();

        // Online softmax (one thread per row)
        if (tid < 64) {
            float mprev = m_s[tid];
            float mx = mprev;
            float* row = &Ss[tid * TPAD];
            #pragma unroll
            for (int c = 0; c < 64; c++) mx = fmaxf(mx, row[c]);
            float fac = __expf(mprev - mx);   // 0 on first tile (exp(-inf))
            float sum = 0.0f;
            #pragma unroll
            for (int c = 0; c < 64; c++) {
                float p = __expf(row[c] - mx);
                row[c] = p;
                sum += p;
            }
            m_s[tid] = mx;
            l_s[tid] = l_s[tid] * fac + sum;
            f_s[tid] = fac;
        }
        __syncthreads();

        // Rescale accumulators
        #pragma unroll
        for (int i = 0; i < 4; i++) {
            float f = f_s[qm + i];
            o[i][0] *= f; o[i][1] *= f; o[i][2] *= f; o[i][3] *= f;
        }

        // O += P @ V
        #pragma unroll
        for (int kc = 0; kc < 64; kc += 4) {
            float ar[4][4];
            #pragma unroll
            for (int i = 0; i < 4; i++)
                *(float4*)&ar[i][0] = *(const float4*)&Ss[(qm + i) * TPAD + kc];
            #pragma unroll
            for (int t = 0; t < 4; t++) {
                float4 bv = *(const float4*)&Vs[(kc + t) * TPAD + cn];
                #pragma unroll
                for (int i = 0; i < 4; i++) {
                    o[i][0] += ar[i][t] * bv.x;
                    o[i][1] += ar[i][t] * bv.y;
                    o[i][2] += ar[i][t] * bv.z;
                    o[i][3] += ar[i][t] * bv.w;
                }
            }
        }
    }

    // Final normalize + store to [B,S,H*dk]
    float* Obase = Op + (size_t)(b * SEQ + q0) * D_MODEL + h * DK;
    #pragma unroll
    for (int i = 0; i < 4; i++) {
        float inv = 1.0f / l_s[qm + i];
        float4 w;
        w.x = o[i][0] * inv; w.y = o[i][1] * inv;
        w.z = o[i][2] * inv; w.w = o[i][3] * inv;
        *(float4*)(Obase + (size_t)(qm + i) * D_MODEL + cn) = w;
    }
}

// ============================================================================
// Launcher
// ============================================================================
extern "C" void kernel_launch(void* const* d_in, const int* in_sizes, int n_in,
                              void* d_out, int out_size)
{
    const float* q    = (const float*)d_in[0];
    const float* k    = (const float*)d_in[1];
    const float* v    = (const float*)d_in[2];
    const float* wq_w = (const float*)d_in[3];
    const float* wq_b = (const float*)d_in[4];
    const float* wk_w = (const float*)d_in[5];
    const float* wk_b = (const float*)d_in[6];
    const float* wv_w = (const float*)d_in[7];
    const float* wv_b = (const float*)d_in[8];
    const float* wo_w = (const float*)d_in[9];
    const float* wo_b = (const float*)d_in[10];

    float *gq, *gk, *gv, *ga;
    cudaGetSymbolAddress((void**)&gq, g_q);
    cudaGetSymbolAddress((void**)&gk, g_k);
    cudaGetSymbolAddress((void**)&gv, g_v);
    cudaGetSymbolAddress((void**)&ga, g_att);

    dim3 gemm_grid(D_MODEL / 128, MTOT / 128);  // (8, 32)

    sgemm_bias<<<gemm_grid, 256>>>(q, wq_w, wq_b, gq, MTOT, D_MODEL, D_MODEL);
    sgemm_bias<<<gemm_grid, 256>>>(k, wk_w, wk_b, gk, MTOT, D_MODEL, D_MODEL);
    sgemm_bias<<<gemm_grid, 256>>>(v, wv_w, wv_b, gv, MTOT, D_MODEL, D_MODEL);

    const int smem_bytes = (4 * 64 * TPAD + 3 * 64) * sizeof(float);  // 70400
    cudaFuncSetAttribute(attn_kernel, cudaFuncAttributeMaxDynamicSharedMemorySize, smem_bytes);
    attn_kernel<<<dim3(SEQ / 64, BATCH * NHEAD), 256, smem_bytes>>>(gq, gk, gv, ga);

    sgemm_bias<<<gemm_grid, 256>>>(ga, wo_w, wo_b, (float*)d_out, MTOT, D_MODEL, D_MODEL);
}

// round 4
// speedup vs baseline: 1.5951x; 1.5951x over previous
#include <cuda_runtime.h>
#include <cstdint>

#define D_MODEL 1024
#define NHEAD   16
#define DK      64
#define BATCH   2
#define SEQ     2048
#define MTOT    (BATCH * SEQ)   // 4096

// Scratch (device globals — no runtime allocation allowed)
__device__ float g_q[MTOT * D_MODEL];
__device__ float g_k[MTOT * D_MODEL];
__device__ float g_v[MTOT * D_MODEL];
__device__ float g_att[MTOT * D_MODEL];

// ============================================================================
// Common helpers
// ============================================================================
__device__ __forceinline__ void cp_async16(uint32_t dst, const void* src) {
    asm volatile("cp.async.ca.shared.global [%0], [%1], 16;"
                 :: "r"(dst), "l"(src) : "memory");
}
__device__ __forceinline__ void cp_commit() {
    asm volatile("cp.async.commit_group;" ::: "memory");
}
__device__ __forceinline__ void cp_wait1() {
    asm volatile("cp.async.wait_group 1;" ::: "memory");
}
__device__ __forceinline__ void cp_wait0() {
    asm volatile("cp.async.wait_group 0;" ::: "memory");
}
__device__ __forceinline__ uint32_t smem_u32(const void* p) {
    uint32_t a;
    asm("{ .reg .u64 t; cvta.to.shared.u64 t, %1; cvt.u32.u64 %0, t; }"
        : "=r"(a) : "l"(p));
    return a;
}
__device__ __forceinline__ uint32_t f2tf32r(float f) {   // round-to-nearest tf32
    uint32_t u;
    asm("cvt.rna.tf32.f32 %0, %1;" : "=r"(u) : "f"(f));
    return u;
}
__device__ __forceinline__ void split_tf32(float v, uint32_t& big, uint32_t& res) {
    uint32_t b = f2tf32r(v);
    big = b;
    res = __float_as_uint(v - __uint_as_float(b));
}
__device__ __forceinline__ void mma_tf32(float& c0, float& c1, float& c2, float& c3,
                                         uint32_t a0, uint32_t a1, uint32_t a2, uint32_t a3,
                                         uint32_t b0, uint32_t b1) {
    asm volatile(
        "mma.sync.aligned.m16n8k8.row.col.f32.tf32.tf32.f32 "
        "{%0,%1,%2,%3}, {%4,%5,%6,%7}, {%8,%9}, {%0,%1,%2,%3};"
        : "+f"(c0), "+f"(c1), "+f"(c2), "+f"(c3)
        : "r"(a0), "r"(a1), "r"(a2), "r"(a3), "r"(b0), "r"(b1));
}

// ============================================================================
// 3xTF32 GEMM:  out[M,N] = X[M,K] @ W[N,K]^T + bias[N]   (fp32-equivalent)
// BM=BN=128, BK=32, 256 thr (8 warps, 2x4), warp tile 64x32.
// ============================================================================
#define BM 128
#define BN 128
#define BK 32
#define PITCH 36
#define STAGE_FLOATS (128 * PITCH)
#define SMEM_GEMM_BYTES (4 * STAGE_FLOATS * 4)  // 73728 B

__global__ __launch_bounds__(256) void gemm_mma(
    const float* __restrict__ X, const float* __restrict__ W,
    const float* __restrict__ bias, float* __restrict__ out,
    int M, int N, int K)
{
    extern __shared__ __align__(16) float smem[];
    float* As[2] = { smem,                    smem + STAGE_FLOATS };
    float* Bs[2] = { smem + 2 * STAGE_FLOATS, smem + 3 * STAGE_FLOATS };

    const int tid  = threadIdx.x;
    const int wid  = tid >> 5;
    const int lane = tid & 31;
    const int gq   = lane >> 2;
    const int tq   = lane & 3;
    const int warp_m = (wid & 1) * 64;
    const int warp_n = (wid >> 1) * 32;
    const int m0 = blockIdx.y * BM;
    const int n0 = blockIdx.x * BN;

    const int ldr = tid >> 3;
    const int ldc = (tid & 7) * 4;
    const float* Xp = X + (size_t)(m0 + ldr) * K + ldc;
    const float* Wp = W + (size_t)(n0 + ldr) * K + ldc;
    const uint32_t aBase[2] = { smem_u32(As[0]), smem_u32(As[1]) };
    const uint32_t bBase[2] = { smem_u32(Bs[0]), smem_u32(Bs[1]) };
    const uint32_t dstOff = (uint32_t)(ldr * PITCH + ldc) * 4;

    float c[4][4][4];
    #pragma unroll
    for (int i = 0; i < 4; i++)
        #pragma unroll
        for (int j = 0; j < 4; j++) {
            c[i][j][0] = 0.f; c[i][j][1] = 0.f; c[i][j][2] = 0.f; c[i][j][3] = 0.f;
        }

    const int NT = K / BK;

    #pragma unroll
    for (int i = 0; i < 4; i++) {
        uint32_t d = dstOff + (uint32_t)(i * 32 * PITCH * 4);
        cp_async16(aBase[0] + d, Xp + (size_t)i * 32 * K);
        cp_async16(bBase[0] + d, Wp + (size_t)i * 32 * K);
    }
    cp_commit();

    int buf = 0;
    for (int kt = 0; kt < NT; kt++) {
        if (kt + 1 < NT) {
            const float* xs = Xp + (kt + 1) * BK;
            const float* ws = Wp + (kt + 1) * BK;
            const int nb = buf ^ 1;
            #pragma unroll
            for (int i = 0; i < 4; i++) {
                uint32_t d = dstOff + (uint32_t)(i * 32 * PITCH * 4);
                cp_async16(aBase[nb] + d, xs + (size_t)i * 32 * K);
                cp_async16(bBase[nb] + d, ws + (size_t)i * 32 * K);
            }
            cp_commit();
            cp_wait1();
        } else {
            cp_wait0();
        }
        __syncthreads();

        const float* Af = As[buf];
        const float* Bf = Bs[buf];
        #pragma unroll
        for (int s = 0; s < 4; s++) {
            const int k0 = s * 8;
            uint32_t b0b[4], b0r[4], b1b[4], b1r[4];
            #pragma unroll
            for (int nt = 0; nt < 4; nt++) {
                const float* bp = Bf + (warp_n + nt * 8 + gq) * PITCH + k0 + tq;
                split_tf32(bp[0], b0b[nt], b0r[nt]);
                split_tf32(bp[4], b1b[nt], b1r[nt]);
            }
            #pragma unroll
            for (int mt = 0; mt < 4; mt++) {
                const float* ap = Af + (warp_m + mt * 16 + gq) * PITCH + k0 + tq;
                uint32_t ab[4], ar[4];
                split_tf32(ap[0],             ab[0], ar[0]);
                split_tf32(ap[8 * PITCH],     ab[1], ar[1]);
                split_tf32(ap[4],             ab[2], ar[2]);
                split_tf32(ap[8 * PITCH + 4], ab[3], ar[3]);
                #pragma unroll
                for (int nt = 0; nt < 4; nt++) {
                    mma_tf32(c[mt][nt][0], c[mt][nt][1], c[mt][nt][2], c[mt][nt][3],
                             ab[0], ab[1], ab[2], ab[3], b0b[nt], b1b[nt]);
                    mma_tf32(c[mt][nt][0], c[mt][nt][1], c[mt][nt][2], c[mt][nt][3],
                             ab[0], ab[1], ab[2], ab[3], b0r[nt], b1r[nt]);
                    mma_tf32(c[mt][nt][0], c[mt][nt][1], c[mt][nt][2], c[mt][nt][3],
                             ar[0], ar[1], ar[2], ar[3], b0b[nt], b1b[nt]);
                }
            }
        }
        __syncthreads();
        buf ^= 1;
    }

    #pragma unroll
    for (int mt = 0; mt < 4; mt++) {
        const int r0 = m0 + warp_m + mt * 16 + gq;
        #pragma unroll
        for (int nt = 0; nt < 4; nt++) {
            const int col = n0 + warp_n + nt * 8 + tq * 2;
            const float bv0 = bias[col], bv1 = bias[col + 1];
            float2 u, v;
            u.x = c[mt][nt][0] + bv0; u.y = c[mt][nt][1] + bv1;
            v.x = c[mt][nt][2] + bv0; v.y = c[mt][nt][3] + bv1;
            *(float2*)&out[(size_t)r0 * N + col] = u;
            *(float2*)&out[(size_t)(r0 + 8) * N + col] = v;
        }
    }
}

// ============================================================================
// Flash attention with tf32 mma.sync.
// CTA = 128 thr = 4 warps, one (b,h,64-query tile). Warp owns 16 query rows.
// Q fragments in registers (pre-scaled 1/8, cvt.rna). K/V double-buffered
// cp.async. P -> smem (warp-private) -> A fragments. Online softmax in regs.
// ============================================================================
#define AT_KP 68
#define AT_VP 72
#define AT_SP 68
#define AT_KS0 0
#define AT_KS1 (64 * AT_KP)
#define AT_VS0 (2 * 64 * AT_KP)
#define AT_VS1 (2 * 64 * AT_KP + 64 * AT_VP)
#define AT_SS  (2 * 64 * AT_KP + 2 * 64 * AT_VP)
#define AT_SMEM_BYTES ((AT_SS + 64 * AT_SP) * 4)   // 89088

__global__ __launch_bounds__(128) void attn_mma(
    const float* __restrict__ Qp, const float* __restrict__ Kp,
    const float* __restrict__ Vp, float* __restrict__ Op)
{
    extern __shared__ __align__(16) float sm[];
    const int tid  = threadIdx.x;
    const int wid  = tid >> 5;
    const int lane = tid & 31;
    const int gq   = lane >> 2;
    const int tq   = lane & 3;
    const int warp_m = wid * 16;
    const int bh = blockIdx.y;
    const int b  = bh >> 4;
    const int h  = bh & 15;
    const int q0 = blockIdx.x * 64;

    const float* Qb = Qp + (size_t)(b * SEQ + q0) * D_MODEL + h * DK;
    const float* Kb = Kp + (size_t)(b * SEQ) * D_MODEL + h * DK;
    const float* Vb = Vp + (size_t)(b * SEQ) * D_MODEL + h * DK;

    // Q fragments: rows warp_m+gq(+8), cols ks*8+tq(+4). Pre-scale 1/sqrt(dk)=1/8.
    uint32_t qa[8][4];
    #pragma unroll
    for (int ks = 0; ks < 8; ks++) {
        const float* qp = Qb + (size_t)(warp_m + gq) * D_MODEL + ks * 8 + tq;
        qa[ks][0] = f2tf32r(qp[0] * 0.125f);
        qa[ks][1] = f2tf32r(qp[8 * D_MODEL] * 0.125f);
        qa[ks][2] = f2tf32r(qp[4] * 0.125f);
        qa[ks][3] = f2tf32r(qp[8 * D_MODEL + 4] * 0.125f);
    }

    float o[8][4];
    #pragma unroll
    for (int i = 0; i < 8; i++) { o[i][0] = 0.f; o[i][1] = 0.f; o[i][2] = 0.f; o[i][3] = 0.f; }
    const float NEG_INF = __int_as_float(0xff800000);
    float m0 = NEG_INF, m1 = NEG_INF, l0 = 0.f, l1 = 0.f;

    // K/V loaders: thread -> row tid>>1, float-col (tid&1)*32, 8 x 16B each.
    const int ldr = tid >> 1;
    const int ldh = (tid & 1) * 32;
    const float* Ksrc = Kb + (size_t)ldr * D_MODEL + ldh;
    const float* Vsrc = Vb + (size_t)ldr * D_MODEL + ldh;
    const uint32_t smb = smem_u32(sm);
    const uint32_t kdst0 = smb + (uint32_t)((AT_KS0 + ldr * AT_KP + ldh) * 4);
    const uint32_t kdst1 = smb + (uint32_t)((AT_KS1 + ldr * AT_KP + ldh) * 4);
    const uint32_t vdst0 = smb + (uint32_t)((AT_VS0 + ldr * AT_VP + ldh) * 4);
    const uint32_t vdst1 = smb + (uint32_t)((AT_VS1 + ldr * AT_VP + ldh) * 4);

    // prologue: tile 0 -> stage 0
    #pragma unroll
    for (int i = 0; i < 8; i++) {
        cp_async16(kdst0 + i * 16, Ksrc + i * 4);
        cp_async16(vdst0 + i * 16, Vsrc + i * 4);
    }
    cp_commit();

    float* Ssf = sm + AT_SS;

    for (int kt = 0; kt < SEQ / 64; kt++) {
        const int buf = kt & 1;
        if (kt + 1 < SEQ / 64) {
            const float* ks2 = Ksrc + (size_t)(kt + 1) * 64 * D_MODEL;
            const float* vs2 = Vsrc + (size_t)(kt + 1) * 64 * D_MODEL;
            const uint32_t kd = buf ? kdst0 : kdst1;
            const uint32_t vd = buf ? vdst0 : vdst1;
            #pragma unroll
            for (int i = 0; i < 8; i++) {
                cp_async16(kd + i * 16, ks2 + i * 4);
                cp_async16(vd + i * 16, vs2 + i * 4);
            }
            cp_commit();
            cp_wait1();
        } else {
            cp_wait0();
        }
        __syncthreads();

        const float* Kst = sm + (buf ? AT_KS1 : AT_KS0);
        const float* Vst = sm + (buf ? AT_VS1 : AT_VS0);

        // ---- S = (Q/8) @ K^T : s[nf] covers key cols nf*8..+7
        float s[8][4];
        #pragma unroll
        for (int i = 0; i < 8; i++) { s[i][0] = 0.f; s[i][1] = 0.f; s[i][2] = 0.f; s[i][3] = 0.f; }
        #pragma unroll
        for (int ks = 0; ks < 8; ks++) {
            uint32_t kb0[8], kb1[8];
            #pragma unroll
            for (int nf = 0; nf < 8; nf++) {
                const float* kp = Kst + (nf * 8 + gq) * AT_KP + ks * 8 + tq;
                kb0[nf] = __float_as_uint(kp[0]);
                kb1[nf] = __float_as_uint(kp[4]);
            }
            #pragma unroll
            for (int nf = 0; nf < 8; nf++)
                mma_tf32(s[nf][0], s[nf][1], s[nf][2], s[nf][3],
                         qa[ks][0], qa[ks][1], qa[ks][2], qa[ks][3], kb0[nf], kb1[nf]);
        }

        // ---- online softmax (row gq -> c0,c1 ; row gq+8 -> c2,c3)
        float mx0 = NEG_INF, mx1 = NEG_INF;
        #pragma unroll
        for (int nf = 0; nf < 8; nf++) {
            mx0 = fmaxf(mx0, fmaxf(s[nf][0], s[nf][1]));
            mx1 = fmaxf(mx1, fmaxf(s[nf][2], s[nf][3]));
        }
        mx0 = fmaxf(mx0, __shfl_xor_sync(0xffffffff, mx0, 1));
        mx0 = fmaxf(mx0, __shfl_xor_sync(0xffffffff, mx0, 2));
        mx1 = fmaxf(mx1, __shfl_xor_sync(0xffffffff, mx1, 1));
        mx1 = fmaxf(mx1, __shfl_xor_sync(0xffffffff, mx1, 2));
        const float m0n = fmaxf(m0, mx0);
        const float m1n = fmaxf(m1, mx1);
        const float fac0 = __expf(m0 - m0n);
        const float fac1 = __expf(m1 - m1n);
        float sum0 = 0.f, sum1 = 0.f;
        #pragma unroll
        for (int nf = 0; nf < 8; nf++) {
            s[nf][0] = __expf(s[nf][0] - m0n);
            s[nf][1] = __expf(s[nf][1] - m0n);
            s[nf][2] = __expf(s[nf][2] - m1n);
            s[nf][3] = __expf(s[nf][3] - m1n);
            sum0 += s[nf][0] + s[nf][1];
            sum1 += s[nf][2] + s[nf][3];
        }
        sum0 += __shfl_xor_sync(0xffffffff, sum0, 1);
        sum0 += __shfl_xor_sync(0xffffffff, sum0, 2);
        sum1 += __shfl_xor_sync(0xffffffff, sum1, 1);
        sum1 += __shfl_xor_sync(0xffffffff, sum1, 2);
        m0 = m0n; m1 = m1n;
        l0 = l0 * fac0 + sum0;
        l1 = l1 * fac1 + sum1;

        // ---- P -> smem (warp-private rows), cvt.rna to tf32
        #pragma unroll
        for (int nf = 0; nf < 8; nf++) {
            float* p0 = Ssf + (warp_m + gq) * AT_SP + nf * 8 + tq * 2;
            float* p1 = Ssf + (warp_m + gq + 8) * AT_SP + nf * 8 + tq * 2;
            p0[0] = __uint_as_float(f2tf32r(s[nf][0]));
            p0[1] = __uint_as_float(f2tf32r(s[nf][1]));
            p1[0] = __uint_as_float(f2tf32r(s[nf][2]));
            p1[1] = __uint_as_float(f2tf32r(s[nf][3]));
        }
        __syncwarp();

        // ---- rescale O
        #pragma unroll
        for (int nf = 0; nf < 8; nf++) {
            o[nf][0] *= fac0; o[nf][1] *= fac0;
            o[nf][2] *= fac1; o[nf][3] *= fac1;
        }

        // ---- O += P @ V : nf covers d cols nf*8..+7, ks covers key chunk
        #pragma unroll
        for (int ks = 0; ks < 8; ks++) {
            const float* pp = Ssf + (warp_m + gq) * AT_SP + ks * 8 + tq;
            uint32_t pa0 = __float_as_uint(pp[0]);
            uint32_t pa1 = __float_as_uint(pp[8 * AT_SP]);
            uint32_t pa2 = __float_as_uint(pp[4]);
            uint32_t pa3 = __float_as_uint(pp[8 * AT_SP + 4]);
            uint32_t vb0[8], vb1[8];
            #pragma unroll
            for (int nf = 0; nf < 8; nf++) {
                const float* vp = Vst + (ks * 8 + tq) * AT_VP + nf * 8 + gq;
                vb0[nf] = __float_as_uint(vp[0]);
                vb1[nf] = __float_as_uint(vp[4 * AT_VP]);
            }
            #pragma unroll
            for (int nf = 0; nf < 8; nf++)
                mma_tf32(o[nf][0], o[nf][1], o[nf][2], o[nf][3],
                         pa0, pa1, pa2, pa3, vb0[nf], vb1[nf]);
        }
        __syncthreads();
    }

    // ---- epilogue: normalize and store
    const float inv0 = 1.f / l0;
    const float inv1 = 1.f / l1;
    float* Ob = Op + (size_t)(b * SEQ + q0 + warp_m + gq) * D_MODEL + h * DK;
    #pragma unroll
    for (int nf = 0; nf < 8; nf++) {
        float2 u, v;
        u.x = o[nf][0] * inv0; u.y = o[nf][1] * inv0;
        v.x = o[nf][2] * inv1; v.y = o[nf][3] * inv1;
        *(float2*)(Ob + nf * 8 + tq * 2) = u;
        *(float2*)(Ob + (size_t)8 * D_MODEL + nf * 8 + tq * 2) = v;
    }
}

// ============================================================================
// Launcher
// ============================================================================
extern "C" void kernel_launch(void* const* d_in, const int* in_sizes, int n_in,
                              void* d_out, int out_size)
{
    const float* q    = (const float*)d_in[0];
    const float* k    = (const float*)d_in[1];
    const float* v    = (const float*)d_in[2];
    const float* wq_w = (const float*)d_in[3];
    const float* wq_b = (const float*)d_in[4];
    const float* wk_w = (const float*)d_in[5];
    const float* wk_b = (const float*)d_in[6];
    const float* wv_w = (const float*)d_in[7];
    const float* wv_b = (const float*)d_in[8];
    const float* wo_w = (const float*)d_in[9];
    const float* wo_b = (const float*)d_in[10];

    float *gq, *gk, *gv, *ga;
    cudaGetSymbolAddress((void**)&gq, g_q);
    cudaGetSymbolAddress((void**)&gk, g_k);
    cudaGetSymbolAddress((void**)&gv, g_v);
    cudaGetSymbolAddress((void**)&ga, g_att);

    cudaFuncSetAttribute(gemm_mma, cudaFuncAttributeMaxDynamicSharedMemorySize,
                         SMEM_GEMM_BYTES);
    cudaFuncSetAttribute(attn_mma, cudaFuncAttributeMaxDynamicSharedMemorySize,
                         AT_SMEM_BYTES);

    dim3 gemm_grid(D_MODEL / BN, MTOT / BM);   // (8, 32)

    gemm_mma<<<gemm_grid, 256, SMEM_GEMM_BYTES>>>(q, wq_w, wq_b, gq, MTOT, D_MODEL, D_MODEL);
    gemm_mma<<<gemm_grid, 256, SMEM_GEMM_BYTES>>>(k, wk_w, wk_b, gk, MTOT, D_MODEL, D_MODEL);
    gemm_mma<<<gemm_grid, 256, SMEM_GEMM_BYTES>>>(v, wv_w, wv_b, gv, MTOT, D_MODEL, D_MODEL);

    attn_mma<<<dim3(SEQ / 64, BATCH * NHEAD), 128, AT_SMEM_BYTES>>>(gq, gk, gv, ga);

    gemm_mma<<<gemm_grid, 256, SMEM_GEMM_BYTES>>>(ga, wo_w, wo_b, (float*)d_out, MTOT, D_MODEL, D_MODEL);
}